// round 1
// baseline (speedup 1.0000x reference)
#include <cuda_runtime.h>

#define NUM_NEURONS 8192
#define INPUT_SIZE  8192
#define BATCH       2048

// Per-neuron collapsed coefficients: out = A + B*a1 + C*a2 + D*a1*a2
__device__ float4 g_coeff[NUM_NEURONS];

// ---------------------------------------------------------------------------
// Precompute kernel: softmax(w[n,:16]) dotted with the constant coefficient
// vectors of the 16 logic ops. 8192 threads total — negligible cost.
// ---------------------------------------------------------------------------
__global__ void coeff_kernel(const float* __restrict__ w) {
    int n = blockIdx.x * blockDim.x + threadIdx.x;
    if (n >= NUM_NEURONS) return;

    const float4* wr = reinterpret_cast<const float4*>(w) + n * 4;
    float v[16];
    float4 t;
    t = wr[0]; v[0]=t.x;  v[1]=t.y;  v[2]=t.z;  v[3]=t.w;
    t = wr[1]; v[4]=t.x;  v[5]=t.y;  v[6]=t.z;  v[7]=t.w;
    t = wr[2]; v[8]=t.x;  v[9]=t.y;  v[10]=t.z; v[11]=t.w;
    t = wr[3]; v[12]=t.x; v[13]=t.y; v[14]=t.z; v[15]=t.w;

    float m = v[0];
#pragma unroll
    for (int i = 1; i < 16; i++) m = fmaxf(m, v[i]);
    float s = 0.0f;
#pragma unroll
    for (int i = 0; i < 16; i++) { v[i] = __expf(v[i] - m); s += v[i]; }
    float inv = 1.0f / s;
#pragma unroll
    for (int i = 0; i < 16; i++) v[i] *= inv;

    // op table (c0 const, c1 a1, c2 a2, c3 p):
    //  0:0  1:p  2:a1-p  3:a1  4:a2-p  5:a2  6:a1+a2-2p  7:a1+a2-p
    //  8:1-(a1+a2-p)  9:1-(a1+a2-2p)  10:1-a2  11:1-a2+p
    // 12:1-a1  13:1-a1+p  14:1-p  15:1
    float A = v[8]+v[9]+v[10]+v[11]+v[12]+v[13]+v[14]+v[15];
    float B = (v[2]+v[3]+v[6]+v[7]) - (v[8]+v[9]+v[12]+v[13]);
    float C = (v[4]+v[5]+v[6]+v[7]) - (v[8]+v[9]+v[10]+v[11]);
    float D = v[1]-v[2]-v[4]-2.0f*v[6]-v[7]+v[8]+2.0f*v[9]+v[11]+v[13]-v[14];

    g_coeff[n] = make_float4(A, B, C, D);
}

// ---------------------------------------------------------------------------
// Main kernel: one block per pair of batch rows. The two 32KB x-rows are
// staged interleaved as float2 in SMEM so a single LDS.64 fetches the gathered
// value for both rows. Each thread produces 4 consecutive neurons per row per
// iteration -> STG.128 output stores.
// ---------------------------------------------------------------------------
__global__ __launch_bounds__(256) void logic_kernel(
    const float* __restrict__ x,
    const int2*  __restrict__ idx,
    float* __restrict__ out)
{
    extern __shared__ float2 xs[];   // [INPUT_SIZE] interleaved {row0, row1}

    const int b0 = blockIdx.x * 2;
    const float4* x0 = reinterpret_cast<const float4*>(x + (size_t)b0 * INPUT_SIZE);
    const float4* x1 = reinterpret_cast<const float4*>(x + (size_t)(b0 + 1) * INPUT_SIZE);

    for (int i = threadIdx.x; i < INPUT_SIZE / 4; i += 256) {
        float4 v0 = x0[i];
        float4 v1 = x1[i];
        int base = i * 4;
        xs[base + 0] = make_float2(v0.x, v1.x);
        xs[base + 1] = make_float2(v0.y, v1.y);
        xs[base + 2] = make_float2(v0.z, v1.z);
        xs[base + 3] = make_float2(v0.w, v1.w);
    }
    __syncthreads();

    float4* out0 = reinterpret_cast<float4*>(out + (size_t)b0 * NUM_NEURONS);
    float4* out1 = reinterpret_cast<float4*>(out + (size_t)(b0 + 1) * NUM_NEURONS);

#pragma unroll
    for (int it = 0; it < NUM_NEURONS / (256 * 4); it++) {
        const int n = it * 1024 + threadIdx.x * 4;
        float4 o0, o1;
        float* p0 = reinterpret_cast<float*>(&o0);
        float* p1 = reinterpret_cast<float*>(&o1);
#pragma unroll
        for (int j = 0; j < 4; j++) {
            int2   id = __ldg(&idx[n + j]);
            float4 c  = g_coeff[n + j];
            float2 a1 = xs[id.x];
            float2 a2 = xs[id.y];
            // out = A + B*a1 + C*a2 + D*a1*a2 = fma(a1, fma(a2,D,B), fma(a2,C,A))
            p0[j] = fmaf(a1.x, fmaf(a2.x, c.w, c.y), fmaf(a2.x, c.z, c.x));
            p1[j] = fmaf(a1.y, fmaf(a2.y, c.w, c.y), fmaf(a2.y, c.z, c.x));
        }
        out0[it * 256 + threadIdx.x] = o0;
        out1[it * 256 + threadIdx.x] = o1;
    }
}

extern "C" void kernel_launch(void* const* d_in, const int* in_sizes, int n_in,
                              void* d_out, int out_size) {
    const float* x    = (const float*)d_in[0];   // [2048, 8192] f32
    const float* w    = (const float*)d_in[1];   // [8192, 16]   f32
    const int2*  conn = (const int2*)d_in[2];    // [8192, 2]    i32
    float* out = (float*)d_out;                  // [2048, 8192] f32

    static const size_t smem = (size_t)INPUT_SIZE * sizeof(float2);   // 64 KB
    cudaFuncSetAttribute(logic_kernel,
                         cudaFuncAttributeMaxDynamicSharedMemorySize, (int)smem);

    coeff_kernel<<<NUM_NEURONS / 256, 256>>>(w);
    logic_kernel<<<BATCH / 2, 256, smem>>>(x, conn, out);
}

// round 2
// speedup vs baseline: 1.3911x; 1.3911x over previous
#include <cuda_runtime.h>

#define NUM_NEURONS 8192
#define INPUT_SIZE  8192
#define BATCH       2048

#define ROWS_PER_BLOCK 4
#define THREADS 512

// Per-neuron collapsed coefficients: out = A + B*a1 + C*a2 + D*a1*a2
__device__ float4 g_coeff[NUM_NEURONS];

// ---------------------------------------------------------------------------
// Precompute: softmax(w[n,:16]) dotted with the constant coefficient vectors
// of the 16 affine-in-(1,a1,a2,a1*a2) logic ops.
// ---------------------------------------------------------------------------
__global__ void coeff_kernel(const float* __restrict__ w) {
    int n = blockIdx.x * blockDim.x + threadIdx.x;
    if (n >= NUM_NEURONS) return;

    const float4* wr = reinterpret_cast<const float4*>(w) + n * 4;
    float v[16];
    float4 t;
    t = wr[0]; v[0]=t.x;  v[1]=t.y;  v[2]=t.z;  v[3]=t.w;
    t = wr[1]; v[4]=t.x;  v[5]=t.y;  v[6]=t.z;  v[7]=t.w;
    t = wr[2]; v[8]=t.x;  v[9]=t.y;  v[10]=t.z; v[11]=t.w;
    t = wr[3]; v[12]=t.x; v[13]=t.y; v[14]=t.z; v[15]=t.w;

    float m = v[0];
#pragma unroll
    for (int i = 1; i < 16; i++) m = fmaxf(m, v[i]);
    float s = 0.0f;
#pragma unroll
    for (int i = 0; i < 16; i++) { v[i] = __expf(v[i] - m); s += v[i]; }
    float inv = 1.0f / s;
#pragma unroll
    for (int i = 0; i < 16; i++) v[i] *= inv;

    //  0:0  1:p  2:a1-p  3:a1  4:a2-p  5:a2  6:a1+a2-2p  7:a1+a2-p
    //  8:1-(a1+a2-p)  9:1-(a1+a2-2p)  10:1-a2  11:1-a2+p
    // 12:1-a1  13:1-a1+p  14:1-p  15:1
    float A = v[8]+v[9]+v[10]+v[11]+v[12]+v[13]+v[14]+v[15];
    float B = (v[2]+v[3]+v[6]+v[7]) - (v[8]+v[9]+v[12]+v[13]);
    float C = (v[4]+v[5]+v[6]+v[7]) - (v[8]+v[9]+v[10]+v[11]);
    float D = v[1]-v[2]-v[4]-2.0f*v[6]-v[7]+v[8]+2.0f*v[9]+v[11]+v[13]-v[14];

    g_coeff[n] = make_float4(A, B, C, D);
}

// ---------------------------------------------------------------------------
// Main kernel: one block per 4 batch rows. The 4 rows are staged in SMEM
// interleaved as one float4 per input column, so one LDS.128 fetches the
// gathered value for all 4 rows. Staging is bank-conflict-free: each thread
// assembles one column's float4 from 4 coalesced row loads, then stores it
// with consecutive lanes at consecutive 16B addresses.
// ---------------------------------------------------------------------------
__global__ __launch_bounds__(THREADS) void logic_kernel(
    const float* __restrict__ x,
    const int2*  __restrict__ idx,
    float* __restrict__ out)
{
    extern __shared__ float4 xs[];   // [INPUT_SIZE], column-interleaved rows 0..3

    const int b0 = blockIdx.x * ROWS_PER_BLOCK;
    const float* xr = x + (size_t)b0 * INPUT_SIZE;

    // Conflict-free staging: 4x coalesced LDG.32 + 1x STS.128 per column.
#pragma unroll
    for (int c = threadIdx.x; c < INPUT_SIZE; c += THREADS) {
        float4 v;
        v.x = __ldg(&xr[c]);
        v.y = __ldg(&xr[c +     INPUT_SIZE]);
        v.z = __ldg(&xr[c + 2 * INPUT_SIZE]);
        v.w = __ldg(&xr[c + 3 * INPUT_SIZE]);
        xs[c] = v;
    }
    __syncthreads();

    float4* out0 = reinterpret_cast<float4*>(out + (size_t)(b0 + 0) * NUM_NEURONS);
    float4* out1 = reinterpret_cast<float4*>(out + (size_t)(b0 + 1) * NUM_NEURONS);
    float4* out2 = reinterpret_cast<float4*>(out + (size_t)(b0 + 2) * NUM_NEURONS);
    float4* out3 = reinterpret_cast<float4*>(out + (size_t)(b0 + 3) * NUM_NEURONS);

#pragma unroll
    for (int it = 0; it < NUM_NEURONS / (THREADS * 4); it++) {
        const int n = it * (THREADS * 4) + threadIdx.x * 4;
        float4 o0, o1, o2, o3;                 // o{r} = row r, neurons n..n+3
        float* p0 = reinterpret_cast<float*>(&o0);
        float* p1 = reinterpret_cast<float*>(&o1);
        float* p2 = reinterpret_cast<float*>(&o2);
        float* p3 = reinterpret_cast<float*>(&o3);
#pragma unroll
        for (int j = 0; j < 4; j++) {
            int2   id = __ldg(&idx[n + j]);
            float4 cf = g_coeff[n + j];
            float4 a1 = xs[id.x];              // rows 0..3 of column id.x
            float4 a2 = xs[id.y];
            // out = A + B*a1 + C*a2 + D*a1*a2
            p0[j] = fmaf(a1.x, fmaf(a2.x, cf.w, cf.y), fmaf(a2.x, cf.z, cf.x));
            p1[j] = fmaf(a1.y, fmaf(a2.y, cf.w, cf.y), fmaf(a2.y, cf.z, cf.x));
            p2[j] = fmaf(a1.z, fmaf(a2.z, cf.w, cf.y), fmaf(a2.z, cf.z, cf.x));
            p3[j] = fmaf(a1.w, fmaf(a2.w, cf.w, cf.y), fmaf(a2.w, cf.z, cf.x));
        }
        const int o = it * THREADS + threadIdx.x;
        out0[o] = o0;
        out1[o] = o1;
        out2[o] = o2;
        out3[o] = o3;
    }
}

extern "C" void kernel_launch(void* const* d_in, const int* in_sizes, int n_in,
                              void* d_out, int out_size) {
    const float* x    = (const float*)d_in[0];   // [2048, 8192] f32
    const float* w    = (const float*)d_in[1];   // [8192, 16]   f32
    const int2*  conn = (const int2*)d_in[2];    // [8192, 2]    i32
    float* out = (float*)d_out;                  // [2048, 8192] f32

    const size_t smem = (size_t)INPUT_SIZE * sizeof(float4);   // 128 KB
    cudaFuncSetAttribute(logic_kernel,
                         cudaFuncAttributeMaxDynamicSharedMemorySize, (int)smem);

    coeff_kernel<<<NUM_NEURONS / 256, 256>>>(w);
    logic_kernel<<<BATCH / ROWS_PER_BLOCK, THREADS, smem>>>(x, conn, out);
}